// round 6
// baseline (speedup 1.0000x reference)
#include <cuda_runtime.h>
#include <math.h>
#include <cstdint>

// Problem sizes
#define Bv 256
#define Tv 512
#define Fv 512
#define Hv 512
#define FH 2048
#define GRIDB 96
#define L1B 32
#define L2B 64

// ---------------- device scratch (no allocations allowed) ----------------
__device__ __align__(16) float gZ1[Bv * FH];      // x[:,T-1,:] @ Wi1 + b1
__device__ __align__(16) float gH1all[Bv * Hv];   // h1 history: gH1all[s] = h1 after step s
__device__ __align__(16) float gH2all[Bv * Hv];   // h2 history (also the "last" matrix)
__device__ int g_cnt1;                            // layer1 arrivals (32 per step)
__device__ int g_cnt2;                            // layer2 arrivals (64 per step)

__device__ __forceinline__ int ld_acq(const int* p) {
    int v;
    asm volatile("ld.acquire.gpu.global.b32 %0, [%1];" : "=r"(v) : "l"(p));
    return v;
}
__device__ __forceinline__ float ldcg(const float* p) {
    float v;
    asm volatile("ld.global.cg.f32 %0, [%1];" : "=f"(v) : "l"(p));
    return v;
}
// fast gate math (MUFU-based)
__device__ __forceinline__ float sigf(float x)  { return 1.0f / (1.0f + __expf(-x)); }
__device__ __forceinline__ float tanhx(float x) { return 1.0f - 2.0f / (__expf(2.0f * x) + 1.0f); }

// ---------------- Phase A: Z1 = x[:,T-1,:] @ Wi1 + b1 (tiled, from validated R3) ----------------
__global__ void gemmZ1(const float* __restrict__ x,
                       const float* __restrict__ Wi1,
                       const float* __restrict__ b1) {
    // fold per-launch counter reset here (runs before lstmPersist on the same stream)
    if (blockIdx.x == 0 && blockIdx.y == 0 && threadIdx.x == 0) { g_cnt1 = 0; g_cnt2 = 0; }

    __shared__ __align__(16) float sx[32][33];
    __shared__ __align__(16) float sw[32 * 128];

    const int tid = threadIdx.x;
    const int c0  = blockIdx.x * 128;
    const int b0  = blockIdx.y * 32;
    const int ct  = tid & 31;
    const int bt  = tid >> 5;

    float acc[4][4] = {};

    for (int f0 = 0; f0 < Fv; f0 += 32) {
        {
            int bb = tid >> 3;
            int ff = (tid & 7) * 4;
            const float* xp = x + (size_t)(b0 + bb) * Tv * Fv + (size_t)(Tv - 1) * Fv + f0 + ff;
            float4 v = *(const float4*)xp;
            sx[bb][ff + 0] = v.x; sx[bb][ff + 1] = v.y;
            sx[bb][ff + 2] = v.z; sx[bb][ff + 3] = v.w;
        }
        #pragma unroll
        for (int r = 0; r < 4; r++) {
            int linear = r * 256 + tid;
            int ff = linear >> 5;
            int cc = (linear & 31) * 4;
            float4 v = *(const float4*)(Wi1 + (size_t)(f0 + ff) * FH + c0 + cc);
            *(float4*)&sw[ff * 128 + cc] = v;
        }
        __syncthreads();
        #pragma unroll
        for (int ff = 0; ff < 32; ff++) {
            float4 wv = *(const float4*)&sw[ff * 128 + ct * 4];
            #pragma unroll
            for (int bi = 0; bi < 4; bi++) {
                float xv = sx[bt * 4 + bi][ff];
                acc[bi][0] = fmaf(xv, wv.x, acc[bi][0]);
                acc[bi][1] = fmaf(xv, wv.y, acc[bi][1]);
                acc[bi][2] = fmaf(xv, wv.z, acc[bi][2]);
                acc[bi][3] = fmaf(xv, wv.w, acc[bi][3]);
            }
        }
        __syncthreads();
    }
    const int c = c0 + ct * 4;
    float4 bv = *(const float4*)(b1 + c);
    #pragma unroll
    for (int bi = 0; bi < 4; bi++) {
        int b = b0 + bt * 4 + bi;
        float4 o;
        o.x = acc[bi][0] + bv.x; o.y = acc[bi][1] + bv.y;
        o.z = acc[bi][2] + bv.z; o.w = acc[bi][3] + bv.w;
        *(float4*)&gZ1[(size_t)b * FH + c] = o;
    }
}

// ---------------- Phase B: persistent, DECOUPLED chains ----------------
// Blocks 0..31  : layer1, 16 units each. Free-runs on g_cnt1 (steps 0..255).
// Blocks 32..95 : layer2, 8 units each. Waits on g_cnt1 (h1 input) + g_cnt2 (steps 1..256).
// h exchanged via full history arrays (no ping-pong, no WAR hazard).
__global__ void __launch_bounds__(256, 1) lstmPersist(
    const float* __restrict__ Wh1, const float* __restrict__ Wi2,
    const float* __restrict__ Wh2, const float* __restrict__ b2,
    const float* __restrict__ Wd,  const float* __restrict__ bd,
    float* __restrict__ out)
{
    __shared__ __align__(16) float sH[1024];
    __shared__ __align__(16) float sPart[1024];
    __shared__ float sZ[64];

    const int tid = threadIdx.x;
    const int bx  = blockIdx.x;

    if (bx < L1B) {
        // ================= layer 1 =================
        const int u0 = bx * 16;
        const int cg = tid & 15;
        const int ks = tid >> 4;
        const int c0 = cg * 4;
        const int g  = c0 >> 4;
        const int col = g * Hv + u0 + (c0 & 15);
        const int kb  = ks * 32;

        float4 rw[32];
        {
            const float* Wp = Wh1 + (size_t)kb * FH + col;
            #pragma unroll
            for (int j = 0; j < 32; j++)
                rw[j] = *(const float4*)(Wp + (size_t)j * FH);
        }
        // reducer thread (tid<64) gate-column for zin / sZ
        const int rcc = (tid >> 4) * Hv + u0 + (tid & 15);
        float cst = 0.f;

        for (int s = 0; s < Bv; s++) {
            // prefetch z-input (independent of barrier)
            float zin = (tid < 64) ? __ldg(gZ1 + (size_t)s * FH + rcc) : 0.f;

            if (s > 0) {
                const int target = L1B * s;
                while (ld_acq(&g_cnt1) < target) { }
                for (int i = tid; i < Hv; i += 256) sH[i] = ldcg(&gH1all[(size_t)(s - 1) * Hv + i]);
            } else {
                for (int i = tid; i < Hv; i += 256) sH[i] = 0.f;
            }
            __syncthreads();

            float4 a = make_float4(0.f, 0.f, 0.f, 0.f);
            #pragma unroll
            for (int j = 0; j < 32; j++) {
                float hk = sH[kb + j];
                a.x = fmaf(hk, rw[j].x, a.x); a.y = fmaf(hk, rw[j].y, a.y);
                a.z = fmaf(hk, rw[j].z, a.z); a.w = fmaf(hk, rw[j].w, a.w);
            }
            *(float4*)&sPart[ks * 64 + c0] = a;
            __syncthreads();

            if (tid < 64) {
                float z = 0.f;
                #pragma unroll
                for (int r = 0; r < 16; r++) z += sPart[r * 64 + tid];
                sZ[tid] = z + zin;
            }
            __syncthreads();

            if (tid < 16) {
                const int u = u0 + tid;
                float zi = sZ[tid], zf = sZ[16 + tid], zg = sZ[32 + tid], zo = sZ[48 + tid];
                cst = sigf(zf) * cst + sigf(zi) * tanhx(zg);
                gH1all[(size_t)s * Hv + u] = sigf(zo) * tanhx(cst);
                __threadfence();
            }
            __syncthreads();
            if (tid == 0) atomicAdd(&g_cnt1, 1);
        }
    } else {
        // ================= layer 2 =================
        const int u0 = (bx - L1B) * 8;
        const int cg = tid & 7;
        const int ks = tid >> 3;
        const int c0 = cg * 4;
        const int g  = c0 >> 3;
        const int col = g * Hv + u0 + (c0 & 7);
        const int kb  = ks * 32;

        float4 rw[32];
        {
            const float* Wp = (kb < Hv ? Wi2 + (size_t)kb * FH
                                       : Wh2 + (size_t)(kb - Hv) * FH) + col;
            #pragma unroll
            for (int j = 0; j < 32; j++)
                rw[j] = *(const float4*)(Wp + (size_t)j * FH);
        }
        float b2r = 0.f;
        if (tid < 32) b2r = b2[(tid >> 3) * Hv + u0 + (tid & 7)];
        float cst = 0.f;

        for (int s = 1; s <= Bv; s++) {
            {   // need h1[s-1]: layer1 step s-1 complete
                const int target1 = L1B * s;
                while (ld_acq(&g_cnt1) < target1) { }
            }
            if (s >= 2) {   // need h2[s-2]: layer2 step s-1 complete
                const int target2 = L2B * (s - 1);
                while (ld_acq(&g_cnt2) < target2) { }
            }

            for (int i = tid; i < Hv; i += 256) sH[i] = ldcg(&gH1all[(size_t)(s - 1) * Hv + i]);
            if (s >= 2) {
                for (int i = tid; i < Hv; i += 256) sH[Hv + i] = ldcg(&gH2all[(size_t)(s - 2) * Hv + i]);
            } else {
                for (int i = tid; i < Hv; i += 256) sH[Hv + i] = 0.f;
            }
            __syncthreads();

            float4 a = make_float4(0.f, 0.f, 0.f, 0.f);
            #pragma unroll
            for (int j = 0; j < 32; j++) {
                float hk = sH[kb + j];
                a.x = fmaf(hk, rw[j].x, a.x); a.y = fmaf(hk, rw[j].y, a.y);
                a.z = fmaf(hk, rw[j].z, a.z); a.w = fmaf(hk, rw[j].w, a.w);
            }
            *(float4*)&sPart[ks * 32 + c0] = a;
            __syncthreads();

            if (tid < 32) {
                float z = 0.f;
                #pragma unroll
                for (int r = 0; r < 32; r++) z += sPart[r * 32 + tid];
                sZ[tid] = z + b2r;
            }
            __syncthreads();

            if (tid < 8) {
                const int u = u0 + tid;
                float zi = sZ[tid], zf = sZ[8 + tid], zg = sZ[16 + tid], zo = sZ[24 + tid];
                cst = sigf(zf) * cst + sigf(zi) * tanhx(zg);
                gH2all[(size_t)(s - 1) * Hv + u] = sigf(zo) * tanhx(cst);
                __threadfence();
            }
            __syncthreads();
            if (tid == 0) atomicAdd(&g_cnt2, 1);
        }
    }

    // ================= fused output GEMM: out = gH2all @ Wd + bd =================
    {
        const int target2 = L2B * Bv;
        while (ld_acq(&g_cnt2) < target2) { }
    }
    const int w    = tid >> 5;
    const int lane = tid & 31;
    for (int m = bx; m < Bv; m += GRIDB) {
        for (int o = w; o < 10; o += 8) {
            float acc = 0.f;
            #pragma unroll
            for (int j = 0; j < 16; j++) {
                int k = lane * 16 + j;
                acc = fmaf(ldcg(&gH2all[(size_t)m * Hv + k]), __ldg(Wd + (size_t)k * 10 + o), acc);
            }
            #pragma unroll
            for (int off = 16; off; off >>= 1)
                acc += __shfl_xor_sync(0xffffffffu, acc, off);
            if (lane == 0) out[m * 10 + o] = acc + __ldg(bd + o);
        }
    }
}

// ---------------- launch ----------------
extern "C" void kernel_launch(void* const* d_in, const int* in_sizes, int n_in,
                              void* d_out, int out_size) {
    (void)in_sizes; (void)n_in; (void)out_size;
    const float* x   = (const float*)d_in[0];
    const float* Wi1 = (const float*)d_in[1];
    const float* Wh1 = (const float*)d_in[2];
    const float* b1  = (const float*)d_in[3];
    const float* Wi2 = (const float*)d_in[4];
    const float* Wh2 = (const float*)d_in[5];
    const float* b2  = (const float*)d_in[6];
    const float* Wd  = (const float*)d_in[7];
    const float* bd  = (const float*)d_in[8];
    float* out = (float*)d_out;

    gemmZ1<<<dim3(16, 8), 256>>>(x, Wi1, b1);
    lstmPersist<<<GRIDB, 256>>>(Wh1, Wi2, Wh2, b2, Wd, bd, out);
}